// round 4
// baseline (speedup 1.0000x reference)
#include <cuda_runtime.h>
#include <cuda_bf16.h>
#include <cstdint>

#define N_NODES 50000
#define N_EDGES 800000
#define DIM 128
#define NBS ((N_NODES + 255) / 256)   // 196 scan blocks

// ---------------- device scratch (no allocations allowed) ----------------
__device__ float g_deg[N_NODES];
__device__ float g_dis[N_NODES];
__device__ int   g_cnt[N_NODES];
__device__ int   g_pre[N_NODES];
__device__ int   g_bsum[NBS];
__device__ int   g_boff[NBS];
__device__ int   g_rowoff[N_NODES + 1];
__device__ int   g_cursor[N_NODES];
__device__ int   g_eid[N_EDGES];
__device__ float g_h[N_NODES * DIM];
__device__ float g_t[N_NODES * DIM];

// ---------------- setup kernels ----------------
__global__ void init_kernel() {
    int i = blockIdx.x * blockDim.x + threadIdx.x;
    if (i < N_NODES) { g_deg[i] = 0.f; g_cnt[i] = 0; }
}

__global__ void count_kernel(const int* __restrict__ ei,
                             const float* __restrict__ ew) {
    int e = blockIdx.x * blockDim.x + threadIdx.x;
    if (e < N_EDGES) {
        int d = ei[N_EDGES + e];        // dst
        atomicAdd(&g_deg[d], ew[e]);
        atomicAdd(&g_cnt[d], 1);
    }
}

// inclusive block scan (blockDim must be multiple of 32, <=1024)
__device__ __forceinline__ int block_scan_incl(int v, int* ws) {
    const int lane = threadIdx.x & 31;
    const int w = threadIdx.x >> 5;
    int incl = v;
    #pragma unroll
    for (int o = 1; o < 32; o <<= 1) {
        int t = __shfl_up_sync(0xffffffffu, incl, o);
        if (lane >= o) incl += t;
    }
    if (lane == 31) ws[w] = incl;
    __syncthreads();
    if (w == 0) {
        int nw = blockDim.x >> 5;
        int s = (lane < nw) ? ws[lane] : 0;
        #pragma unroll
        for (int o = 1; o < 32; o <<= 1) {
            int t = __shfl_up_sync(0xffffffffu, s, o);
            if (lane >= o) s += t;
        }
        if (lane < nw) ws[lane] = s;
    }
    __syncthreads();
    if (w > 0) incl += ws[w - 1];
    return incl;
}

// pass 1: per-block exclusive pre-scan + block sums; fused dis = rsqrt(deg+1)
__global__ __launch_bounds__(256) void scan1_kernel() {
    __shared__ int ws[8];
    int i = blockIdx.x * 256 + threadIdx.x;
    int v = (i < N_NODES) ? g_cnt[i] : 0;
    int incl = block_scan_incl(v, ws);
    if (i < N_NODES) g_pre[i] = incl - v;
    if (threadIdx.x == 255) g_bsum[blockIdx.x] = incl;
    if (i < N_NODES) g_dis[i] = rsqrtf(g_deg[i] + 1.0f);
}

// pass 2: scan the 196 block sums (single block)
__global__ __launch_bounds__(256) void scan2_kernel() {
    __shared__ int ws[8];
    int t = threadIdx.x;
    int v = (t < NBS) ? g_bsum[t] : 0;
    int incl = block_scan_incl(v, ws);
    if (t < NBS) g_boff[t] = incl - v;
}

// pass 3: add block offsets -> rowoff / cursor
__global__ __launch_bounds__(256) void scan3_kernel() {
    int i = blockIdx.x * 256 + threadIdx.x;
    if (i < N_NODES) {
        int r = g_pre[i] + g_boff[blockIdx.x];
        g_rowoff[i] = r;
        g_cursor[i] = r;
    }
    if (i == 0) g_rowoff[N_NODES] = N_EDGES;
}

__global__ void fill_kernel(const int* __restrict__ ei) {
    int e = blockIdx.x * blockDim.x + threadIdx.x;
    if (e < N_EDGES) {
        int d = ei[N_EDGES + e];
        int pos = atomicAdd(&g_cursor[d], 1);
        g_eid[pos] = e;
    }
}

// ---------------- f32x2 helpers (sm_103a packed fp32 pipe) ----------------
__device__ __forceinline__ uint64_t pack2(float lo, float hi) {
    uint64_t r;
    asm("mov.b64 %0, {%1, %2};" : "=l"(r) : "f"(lo), "f"(hi));
    return r;
}
__device__ __forceinline__ void unpack2(uint64_t v, float& lo, float& hi) {
    asm("mov.b64 {%0, %1}, %2;" : "=f"(lo), "=f"(hi) : "l"(v));
}
__device__ __forceinline__ void fma2(uint64_t& acc, uint64_t a, uint64_t b) {
    asm("fma.rn.f32x2 %0, %1, %2, %0;" : "+l"(acc) : "l"(a), "l"(b));
}

// ---------------- GEMM: C[M,128] = A[M,128] @ W[128,128] ----------------
// 256 threads, 64-row tile. Thread (wy, lane) computes 8 rows x 4 cols,
// accumulating in packed f32x2 pairs (FFMA2: 2 flops/instr).
#define MT 64
__global__ __launch_bounds__(256) void gemm_kernel(const float* __restrict__ A,
                                                   const float* __restrict__ W,
                                                   float* __restrict__ C) {
    __shared__ float sA[MT][DIM];     // 32 KB
    const int r0 = blockIdx.x * MT;
    const int tid = threadIdx.x;
    const int lane = tid & 31;
    const int wy = tid >> 5;          // 8 row-groups of 8 rows
    const int c0 = lane * 4;

    #pragma unroll
    for (int it = 0; it < 8; it++) {
        int idx = tid + it * 256;     // float4 index, 0..2047
        int r = idx >> 5;
        int k4 = idx & 31;
        float4 v = make_float4(0.f, 0.f, 0.f, 0.f);
        if (r0 + r < N_NODES)
            v = *(const float4*)(A + (size_t)(r0 + r) * DIM + k4 * 4);
        *(float4*)&sA[r][k4 * 4] = v;
    }
    __syncthreads();

    uint64_t acc01[8], acc23[8];
    #pragma unroll
    for (int rr = 0; rr < 8; rr++) { acc01[rr] = 0ull; acc23[rr] = 0ull; }

    #pragma unroll 4
    for (int k = 0; k < DIM; k++) {
        float4 wv = *(const float4*)(W + k * DIM + c0);
        uint64_t w01 = pack2(wv.x, wv.y);
        uint64_t w23 = pack2(wv.z, wv.w);
        #pragma unroll
        for (int rr = 0; rr < 8; rr++) {
            float a = sA[wy * 8 + rr][k];
            uint64_t aa = pack2(a, a);
            fma2(acc01[rr], aa, w01);
            fma2(acc23[rr], aa, w23);
        }
    }

    #pragma unroll
    for (int rr = 0; rr < 8; rr++) {
        int r = r0 + wy * 8 + rr;
        if (r < N_NODES) {
            float4 o;
            unpack2(acc01[rr], o.x, o.y);
            unpack2(acc23[rr], o.z, o.w);
            *(float4*)(C + (size_t)r * DIM + c0) = o;
        }
    }
}

// ---------------- aggregation: one block (4 warps) per node ----------------
// Each warp reads full 512B h[src] rows (LDG.128/lane); warps split edges.
// 2-way unrolled edge loop for MLP.
__global__ __launch_bounds__(128) void agg_kernel(const float* __restrict__ h,
                                                  const float* __restrict__ bias,
                                                  float* __restrict__ out,
                                                  const int* __restrict__ ei,
                                                  const float* __restrict__ ew,
                                                  int do_relu) {
    const int i = blockIdx.x;
    const int tid = threadIdx.x;
    const int w = tid >> 5;
    const int l = tid & 31;
    const float di = g_dis[i];

    const int beg = g_rowoff[i];
    const int end = g_rowoff[i + 1];

    __shared__ int   s_s[128];
    __shared__ float s_w[128];
    __shared__ float sred[3 * 128];

    float4 acc  = make_float4(0.f, 0.f, 0.f, 0.f);
    float4 acc2 = make_float4(0.f, 0.f, 0.f, 0.f);

    for (int base = beg; base < end; base += 128) {
        int n = end - base;
        if (n > 128) n = 128;
        if (tid < n) {
            int e = g_eid[base + tid];
            int s = ei[e];
            s_s[tid] = s;
            s_w[tid] = g_dis[s] * ew[e] * di;
        }
        __syncthreads();
        int j = w;
        for (; j + 4 < n; j += 8) {
            const float4 hv1 = *(const float4*)(h + (size_t)s_s[j] * DIM + l * 4);
            const float4 hv2 = *(const float4*)(h + (size_t)s_s[j + 4] * DIM + l * 4);
            float wt1 = s_w[j];
            float wt2 = s_w[j + 4];
            acc.x  += hv1.x * wt1; acc.y  += hv1.y * wt1;
            acc.z  += hv1.z * wt1; acc.w  += hv1.w * wt1;
            acc2.x += hv2.x * wt2; acc2.y += hv2.y * wt2;
            acc2.z += hv2.z * wt2; acc2.w += hv2.w * wt2;
        }
        if (j < n) {
            const float4 hv = *(const float4*)(h + (size_t)s_s[j] * DIM + l * 4);
            float wt = s_w[j];
            acc.x += hv.x * wt; acc.y += hv.y * wt;
            acc.z += hv.z * wt; acc.w += hv.w * wt;
        }
        __syncthreads();
    }

    acc.x += acc2.x; acc.y += acc2.y; acc.z += acc2.z; acc.w += acc2.w;

    if (w > 0)
        *(float4*)&sred[(w - 1) * 128 + l * 4] = acc;
    __syncthreads();

    if (w == 0) {
        #pragma unroll
        for (int p = 0; p < 3; p++) {
            float4 o = *(const float4*)&sred[p * 128 + l * 4];
            acc.x += o.x; acc.y += o.y; acc.z += o.z; acc.w += o.w;
        }
        const float dd = di * di;
        const float4 hi = *(const float4*)(h + (size_t)i * DIM + l * 4);
        const float4 bv = *(const float4*)(bias + l * 4);
        acc.x += hi.x * dd + bv.x;
        acc.y += hi.y * dd + bv.y;
        acc.z += hi.z * dd + bv.z;
        acc.w += hi.w * dd + bv.w;
        if (do_relu) {
            acc.x = fmaxf(acc.x, 0.f);
            acc.y = fmaxf(acc.y, 0.f);
            acc.z = fmaxf(acc.z, 0.f);
            acc.w = fmaxf(acc.w, 0.f);
        }
        *(float4*)(out + (size_t)i * DIM + l * 4) = acc;
    }
}

// ---------------- launch ----------------
extern "C" void kernel_launch(void* const* d_in, const int* in_sizes, int n_in,
                              void* d_out, int out_size) {
    const float* x  = (const float*)d_in[0];
    const int*   ei = (const int*)d_in[1];
    const float* ew = (const float*)d_in[2];
    const float* W1 = (const float*)d_in[3];
    const float* b1 = (const float*)d_in[4];
    const float* W2 = (const float*)d_in[5];
    const float* b2 = (const float*)d_in[6];
    float* out = (float*)d_out;

    float* h_buf; cudaGetSymbolAddress((void**)&h_buf, g_h);
    float* t_buf; cudaGetSymbolAddress((void**)&t_buf, g_t);

    const int NB_N = (N_NODES + 255) / 256;
    const int NB_E = (N_EDGES + 255) / 256;
    const int NB_G = (N_NODES + MT - 1) / MT;

    // graph structure setup
    init_kernel<<<NB_N, 256>>>();
    count_kernel<<<NB_E, 256>>>(ei, ew);
    scan1_kernel<<<NBS, 256>>>();      // also computes g_dis
    scan2_kernel<<<1, 256>>>();
    scan3_kernel<<<NBS, 256>>>();
    fill_kernel<<<NB_E, 256>>>(ei);

    // layer 1
    gemm_kernel<<<NB_G, 256>>>(x, W1, h_buf);
    agg_kernel<<<N_NODES, 128>>>(h_buf, b1, t_buf, ei, ew, 1);

    // layer 2
    gemm_kernel<<<NB_G, 256>>>(t_buf, W2, h_buf);
    agg_kernel<<<N_NODES, 128>>>(h_buf, b2, out, ei, ew, 0);
}

// round 5
// speedup vs baseline: 1.2067x; 1.2067x over previous
#include <cuda_runtime.h>
#include <cuda_bf16.h>

#define N_NODES 50000
#define N_EDGES 800000
#define DIM 128
#define NBS ((N_NODES + 255) / 256)   // 196 scan blocks

// ---------------- device scratch (no allocations allowed) ----------------
__device__ float g_deg[N_NODES];
__device__ float g_dis[N_NODES];
__device__ int   g_cnt[N_NODES];
__device__ int   g_pre[N_NODES];
__device__ int   g_bsum[NBS];
__device__ int   g_boff[NBS];
__device__ int   g_rowoff[N_NODES + 1];
__device__ int   g_cursor[N_NODES];
__device__ int   g_eid[N_EDGES];
__device__ float g_h[N_NODES * DIM];
__device__ float g_t[N_NODES * DIM];

// ---------------- setup kernels ----------------
__global__ void init_kernel() {
    int i = blockIdx.x * blockDim.x + threadIdx.x;
    if (i < N_NODES) { g_deg[i] = 0.f; g_cnt[i] = 0; }
}

__global__ void count_kernel(const int* __restrict__ ei,
                             const float* __restrict__ ew) {
    int e = blockIdx.x * blockDim.x + threadIdx.x;
    if (e < N_EDGES) {
        int d = ei[N_EDGES + e];        // dst
        atomicAdd(&g_deg[d], ew[e]);
        atomicAdd(&g_cnt[d], 1);
    }
}

// inclusive block scan (blockDim must be multiple of 32, <=1024)
__device__ __forceinline__ int block_scan_incl(int v, int* ws) {
    const int lane = threadIdx.x & 31;
    const int w = threadIdx.x >> 5;
    int incl = v;
    #pragma unroll
    for (int o = 1; o < 32; o <<= 1) {
        int t = __shfl_up_sync(0xffffffffu, incl, o);
        if (lane >= o) incl += t;
    }
    if (lane == 31) ws[w] = incl;
    __syncthreads();
    if (w == 0) {
        int nw = blockDim.x >> 5;
        int s = (lane < nw) ? ws[lane] : 0;
        #pragma unroll
        for (int o = 1; o < 32; o <<= 1) {
            int t = __shfl_up_sync(0xffffffffu, s, o);
            if (lane >= o) s += t;
        }
        if (lane < nw) ws[lane] = s;
    }
    __syncthreads();
    if (w > 0) incl += ws[w - 1];
    return incl;
}

// pass 1: per-block exclusive pre-scan + block sums; fused dis = rsqrt(deg+1)
__global__ __launch_bounds__(256) void scan1_kernel() {
    __shared__ int ws[8];
    int i = blockIdx.x * 256 + threadIdx.x;
    int v = (i < N_NODES) ? g_cnt[i] : 0;
    int incl = block_scan_incl(v, ws);
    if (i < N_NODES) g_pre[i] = incl - v;
    if (threadIdx.x == 255) g_bsum[blockIdx.x] = incl;
    if (i < N_NODES) g_dis[i] = rsqrtf(g_deg[i] + 1.0f);
}

// pass 2: scan the 196 block sums (single block)
__global__ __launch_bounds__(256) void scan2_kernel() {
    __shared__ int ws[8];
    int t = threadIdx.x;
    int v = (t < NBS) ? g_bsum[t] : 0;
    int incl = block_scan_incl(v, ws);
    if (t < NBS) g_boff[t] = incl - v;
}

// pass 3: add block offsets -> rowoff / cursor
__global__ __launch_bounds__(256) void scan3_kernel() {
    int i = blockIdx.x * 256 + threadIdx.x;
    if (i < N_NODES) {
        int r = g_pre[i] + g_boff[blockIdx.x];
        g_rowoff[i] = r;
        g_cursor[i] = r;
    }
    if (i == 0) g_rowoff[N_NODES] = N_EDGES;
}

__global__ void fill_kernel(const int* __restrict__ ei) {
    int e = blockIdx.x * blockDim.x + threadIdx.x;
    if (e < N_EDGES) {
        int d = ei[N_EDGES + e];
        int pos = atomicAdd(&g_cursor[d], 1);
        g_eid[pos] = e;
    }
}

// ---------------- GEMM: C[M,128] = A[M,128] @ W[128,128] ----------------
// 256 threads, 64-row tile. Thread (wy, lane) computes 8 rows x 4 cols.
// (proven Round-3 version)
#define MT 64
__global__ __launch_bounds__(256) void gemm_kernel(const float* __restrict__ A,
                                                   const float* __restrict__ W,
                                                   float* __restrict__ C) {
    __shared__ float sA[MT][DIM];     // 32 KB
    const int r0 = blockIdx.x * MT;
    const int tid = threadIdx.x;
    const int lane = tid & 31;
    const int wy = tid >> 5;          // 8 row-groups of 8 rows
    const int c0 = lane * 4;

    #pragma unroll
    for (int it = 0; it < 8; it++) {
        int idx = tid + it * 256;     // float4 index, 0..2047
        int r = idx >> 5;
        int k4 = idx & 31;
        float4 v = make_float4(0.f, 0.f, 0.f, 0.f);
        if (r0 + r < N_NODES)
            v = *(const float4*)(A + (size_t)(r0 + r) * DIM + k4 * 4);
        *(float4*)&sA[r][k4 * 4] = v;
    }
    __syncthreads();

    float acc[8][4];
    #pragma unroll
    for (int rr = 0; rr < 8; rr++)
        #pragma unroll
        for (int cc = 0; cc < 4; cc++) acc[rr][cc] = 0.f;

    #pragma unroll 4
    for (int k = 0; k < DIM; k++) {
        float4 wv = *(const float4*)(W + k * DIM + c0);
        #pragma unroll
        for (int rr = 0; rr < 8; rr++) {
            float a = sA[wy * 8 + rr][k];
            acc[rr][0] += a * wv.x;
            acc[rr][1] += a * wv.y;
            acc[rr][2] += a * wv.z;
            acc[rr][3] += a * wv.w;
        }
    }

    #pragma unroll
    for (int rr = 0; rr < 8; rr++) {
        int r = r0 + wy * 8 + rr;
        if (r < N_NODES)
            *(float4*)(C + (size_t)r * DIM + c0) =
                make_float4(acc[rr][0], acc[rr][1], acc[rr][2], acc[rr][3]);
    }
}

// ---------------- aggregation: one WARP per node ----------------
// 8 warps/block, each warp owns node i = blockIdx.x*8 + warp.
// Lanes cooperatively fetch <=32 edge records; shfl broadcasts (src, wt);
// each lane FMAs its 4 columns from an LDG.128 row gather.
// No __syncthreads, no smem, no cross-warp reduce.
__global__ __launch_bounds__(256) void agg_kernel(const float* __restrict__ h,
                                                  const float* __restrict__ bias,
                                                  float* __restrict__ out,
                                                  const int* __restrict__ ei,
                                                  const float* __restrict__ ew,
                                                  int do_relu) {
    const int w = threadIdx.x >> 5;
    const int l = threadIdx.x & 31;
    const int i = blockIdx.x * 8 + w;
    if (i >= N_NODES) return;

    const float di = g_dis[i];
    const int beg = g_rowoff[i];
    const int end = g_rowoff[i + 1];

    float4 acc  = make_float4(0.f, 0.f, 0.f, 0.f);
    float4 acc2 = make_float4(0.f, 0.f, 0.f, 0.f);

    for (int base = beg; base < end; base += 32) {
        int n = end - base;
        if (n > 32) n = 32;
        // lanes 0..n-1 fetch one edge record each
        int s = 0;
        float wt = 0.f;
        if (l < n) {
            int e = g_eid[base + l];
            s = ei[e];
            wt = g_dis[s] * ew[e] * di;
        }
        int j = 0;
        for (; j + 1 < n; j += 2) {
            int   s1 = __shfl_sync(0xffffffffu, s,  j);
            float w1 = __shfl_sync(0xffffffffu, wt, j);
            int   s2 = __shfl_sync(0xffffffffu, s,  j + 1);
            float w2 = __shfl_sync(0xffffffffu, wt, j + 1);
            const float4 h1 = *(const float4*)(h + (size_t)s1 * DIM + l * 4);
            const float4 h2 = *(const float4*)(h + (size_t)s2 * DIM + l * 4);
            acc.x  += h1.x * w1; acc.y  += h1.y * w1;
            acc.z  += h1.z * w1; acc.w  += h1.w * w1;
            acc2.x += h2.x * w2; acc2.y += h2.y * w2;
            acc2.z += h2.z * w2; acc2.w += h2.w * w2;
        }
        if (j < n) {
            int   s1 = __shfl_sync(0xffffffffu, s,  j);
            float w1 = __shfl_sync(0xffffffffu, wt, j);
            const float4 h1 = *(const float4*)(h + (size_t)s1 * DIM + l * 4);
            acc.x += h1.x * w1; acc.y += h1.y * w1;
            acc.z += h1.z * w1; acc.w += h1.w * w1;
        }
    }

    acc.x += acc2.x; acc.y += acc2.y; acc.z += acc2.z; acc.w += acc2.w;

    const float dd = di * di;
    const float4 hi = *(const float4*)(h + (size_t)i * DIM + l * 4);
    const float4 bv = *(const float4*)(bias + l * 4);
    acc.x += hi.x * dd + bv.x;
    acc.y += hi.y * dd + bv.y;
    acc.z += hi.z * dd + bv.z;
    acc.w += hi.w * dd + bv.w;
    if (do_relu) {
        acc.x = fmaxf(acc.x, 0.f);
        acc.y = fmaxf(acc.y, 0.f);
        acc.z = fmaxf(acc.z, 0.f);
        acc.w = fmaxf(acc.w, 0.f);
    }
    *(float4*)(out + (size_t)i * DIM + l * 4) = acc;
}

// ---------------- launch ----------------
extern "C" void kernel_launch(void* const* d_in, const int* in_sizes, int n_in,
                              void* d_out, int out_size) {
    const float* x  = (const float*)d_in[0];
    const int*   ei = (const int*)d_in[1];
    const float* ew = (const float*)d_in[2];
    const float* W1 = (const float*)d_in[3];
    const float* b1 = (const float*)d_in[4];
    const float* W2 = (const float*)d_in[5];
    const float* b2 = (const float*)d_in[6];
    float* out = (float*)d_out;

    float* h_buf; cudaGetSymbolAddress((void**)&h_buf, g_h);
    float* t_buf; cudaGetSymbolAddress((void**)&t_buf, g_t);

    const int NB_N = (N_NODES + 255) / 256;
    const int NB_E = (N_EDGES + 255) / 256;
    const int NB_G = (N_NODES + MT - 1) / MT;
    const int NB_A = (N_NODES + 7) / 8;

    // graph structure setup
    init_kernel<<<NB_N, 256>>>();
    count_kernel<<<NB_E, 256>>>(ei, ew);
    scan1_kernel<<<NBS, 256>>>();      // also computes g_dis
    scan2_kernel<<<1, 256>>>();
    scan3_kernel<<<NBS, 256>>>();
    fill_kernel<<<NB_E, 256>>>(ei);

    // layer 1
    gemm_kernel<<<NB_G, 256>>>(x, W1, h_buf);
    agg_kernel<<<NB_A, 256>>>(h_buf, b1, t_buf, ei, ew, 1);

    // layer 2
    gemm_kernel<<<NB_G, 256>>>(t_buf, W2, h_buf);
    agg_kernel<<<NB_A, 256>>>(h_buf, b2, out, ei, ew, 0);
}